// round 1
// baseline (speedup 1.0000x reference)
#include <cuda_runtime.h>

// Spherical: out = x * |s|  (reference is x @ (|s|*I)^T, i.e. an elementwise scale)
// Pure HBM-streaming kernel: 268 MB total traffic, floor ~34 us on GB300.

__global__ void __launch_bounds__(256) spherical_scale_kernel(
    const float4* __restrict__ x,
    const float* __restrict__ s,
    float4* __restrict__ out,
    int n4)
{
    int i = blockIdx.x * blockDim.x + threadIdx.x;
    if (i >= n4) return;
    float scale = fabsf(__ldg(s));
    float4 v = x[i];
    v.x *= scale;
    v.y *= scale;
    v.z *= scale;
    v.w *= scale;
    out[i] = v;
}

extern "C" void kernel_launch(void* const* d_in, const int* in_sizes, int n_in,
                              void* d_out, int out_size)
{
    const float4* x = (const float4*)d_in[0];
    const float*  s = (const float*)d_in[1];
    float4* out = (float4*)d_out;

    int n  = in_sizes[0];        // 8192*4096 = 33554432
    int n4 = n / 4;              // divisible by 4

    int threads = 256;
    int blocks = (n4 + threads - 1) / threads;
    spherical_scale_kernel<<<blocks, threads>>>(x, s, out, n4);
}

// round 2
// speedup vs baseline: 1.0129x; 1.0129x over previous
#include <cuda_runtime.h>

// Spherical: out = x * |s|  — pure HBM stream (268 MB), floor ~34us @ 8TB/s.
// R2: 4 independent float4 loads per thread (MLP_p1=4) + streaming cache hints.

__global__ void __launch_bounds__(256) spherical_scale_kernel(
    const float4* __restrict__ x,
    const float* __restrict__ s,
    float4* __restrict__ out,
    int n4)
{
    const float scale = fabsf(__ldg(s));

    // Each block covers 256*4 float4s; within block, thread t handles
    // indices base + t + k*256 (coalesced per k).
    int base = blockIdx.x * (blockDim.x * 4) + threadIdx.x;

    float4 v0, v1, v2, v3;
    int i0 = base;
    int i1 = base + 256;
    int i2 = base + 512;
    int i3 = base + 768;

    if (i3 < n4) {
        // Fast path: front-batch all 4 loads (independent, MLP=4).
        v0 = __ldcs(&x[i0]);
        v1 = __ldcs(&x[i1]);
        v2 = __ldcs(&x[i2]);
        v3 = __ldcs(&x[i3]);

        v0.x *= scale; v0.y *= scale; v0.z *= scale; v0.w *= scale;
        v1.x *= scale; v1.y *= scale; v1.z *= scale; v1.w *= scale;
        v2.x *= scale; v2.y *= scale; v2.z *= scale; v2.w *= scale;
        v3.x *= scale; v3.y *= scale; v3.z *= scale; v3.w *= scale;

        __stcs(&out[i0], v0);
        __stcs(&out[i1], v1);
        __stcs(&out[i2], v2);
        __stcs(&out[i3], v3);
    } else {
        // Tail (not hit for 8192x4096, but keep it general).
        #pragma unroll
        for (int k = 0; k < 4; k++) {
            int i = base + k * 256;
            if (i < n4) {
                float4 v = __ldcs(&x[i]);
                v.x *= scale; v.y *= scale; v.z *= scale; v.w *= scale;
                __stcs(&out[i], v);
            }
        }
    }
}

extern "C" void kernel_launch(void* const* d_in, const int* in_sizes, int n_in,
                              void* d_out, int out_size)
{
    const float4* x = (const float4*)d_in[0];
    const float*  s = (const float*)d_in[1];
    float4* out = (float4*)d_out;

    int n  = in_sizes[0];        // 8192*4096 = 33554432
    int n4 = n / 4;              // 8388608

    int threads = 256;
    int per_block = threads * 4;                 // 1024 float4 per block
    int blocks = (n4 + per_block - 1) / per_block;  // 8192
    spherical_scale_kernel<<<blocks, threads>>>(x, s, out, n4);
}

// round 3
// speedup vs baseline: 1.0368x; 1.0235x over previous
#include <cuda_runtime.h>

// Spherical: out = x * |s| — pure HBM stream (268 MB).
// R3: 8 front-batched float4 loads per thread (128B), exact-cover grid,
//     no bounds checks, streaming cache ops.

__global__ void __launch_bounds__(256) spherical_scale_kernel(
    const float4* __restrict__ x,
    const float* __restrict__ s,
    float4* __restrict__ out)
{
    const float scale = fabsf(__ldg(s));

    // Block covers 256*8 = 2048 float4s. Thread t handles base + t + k*256.
    const int base = blockIdx.x * (256 * 8) + threadIdx.x;
    const float4* __restrict__ xp = x + base;
    float4* __restrict__ op = out + base;

    // Front-batch all 8 independent loads (MLP_p1 = 8).
    float4 v0 = __ldcs(xp + 0 * 256);
    float4 v1 = __ldcs(xp + 1 * 256);
    float4 v2 = __ldcs(xp + 2 * 256);
    float4 v3 = __ldcs(xp + 3 * 256);
    float4 v4 = __ldcs(xp + 4 * 256);
    float4 v5 = __ldcs(xp + 5 * 256);
    float4 v6 = __ldcs(xp + 6 * 256);
    float4 v7 = __ldcs(xp + 7 * 256);

    v0.x *= scale; v0.y *= scale; v0.z *= scale; v0.w *= scale;
    v1.x *= scale; v1.y *= scale; v1.z *= scale; v1.w *= scale;
    v2.x *= scale; v2.y *= scale; v2.z *= scale; v2.w *= scale;
    v3.x *= scale; v3.y *= scale; v3.z *= scale; v3.w *= scale;
    v4.x *= scale; v4.y *= scale; v4.z *= scale; v4.w *= scale;
    v5.x *= scale; v5.y *= scale; v5.z *= scale; v5.w *= scale;
    v6.x *= scale; v6.y *= scale; v6.z *= scale; v6.w *= scale;
    v7.x *= scale; v7.y *= scale; v7.z *= scale; v7.w *= scale;

    __stcs(op + 0 * 256, v0);
    __stcs(op + 1 * 256, v1);
    __stcs(op + 2 * 256, v2);
    __stcs(op + 3 * 256, v3);
    __stcs(op + 4 * 256, v4);
    __stcs(op + 5 * 256, v5);
    __stcs(op + 6 * 256, v6);
    __stcs(op + 7 * 256, v7);
}

// Generic fallback for sizes not divisible by the tile (not used at 8192x4096).
__global__ void __launch_bounds__(256) spherical_scale_tail(
    const float* __restrict__ x,
    const float* __restrict__ s,
    float* __restrict__ out,
    int start, int n)
{
    const float scale = fabsf(__ldg(s));
    int i = start + blockIdx.x * blockDim.x + threadIdx.x;
    if (i < n) out[i] = x[i] * scale;
}

extern "C" void kernel_launch(void* const* d_in, const int* in_sizes, int n_in,
                              void* d_out, int out_size)
{
    const float4* x = (const float4*)d_in[0];
    const float*  s = (const float*)d_in[1];
    float4* out = (float4*)d_out;

    const int n  = in_sizes[0];            // 33554432
    const int n4 = n / 4;                  // 8388608
    const int per_block = 256 * 8;         // 2048 float4 per block
    const int blocks = n4 / per_block;     // 4096 (exact)

    spherical_scale_kernel<<<blocks, 256>>>(x, s, out);

    // Handle any remainder elements (none for this shape).
    const int covered = blocks * per_block * 4;
    if (covered < n) {
        const int rem = n - covered;
        spherical_scale_tail<<<(rem + 255) / 256, 256>>>(
            (const float*)d_in[0], s, (float*)d_out, covered, n);
    }
}